// round 5
// baseline (speedup 1.0000x reference)
#include <cuda_runtime.h>
#include <cstdint>

#define BATCHN 8
#define TT 2048
#define EE 1024
#define DD 128
#define MTOT (BATCHN*TT)

// Scratch for Q,K,V projections (8 MB each) — __device__ globals per allocation rules.
__device__ float g_q[MTOT*DD];
__device__ float g_k[MTOT*DD];
__device__ float g_v[MTOT*DD];

typedef unsigned long long ull;

__device__ __forceinline__ ull packf2(float x, float y) {
  ull r;
  asm("mov.b64 %0, {%1, %2};" : "=l"(r) : "f"(x), "f"(y));
  return r;
}
__device__ __forceinline__ void fma2(ull& c, ull a, ull b) {
  asm("fma.rn.f32x2 %0, %1, %2, %0;" : "+l"(c) : "l"(a), "l"(b));
}
__device__ __forceinline__ ull mul2(ull a, ull b) {
  ull r;
  asm("mul.rn.f32x2 %0, %1, %2;" : "=l"(r) : "l"(a), "l"(b));
  return r;
}
union F2U { ull u; float2 f; };

// ---------------------------------------------------------------------------
// QKV projection (unchanged from R4 — measured at the scalar FFMA roofline).
// ---------------------------------------------------------------------------
__global__ __launch_bounds__(256) void qkv_gemm_kernel(
    const float* __restrict__ X, const float* __restrict__ Wq,
    const float* __restrict__ Wk, const float* __restrict__ Wv) {
  __shared__ float Xs[8][128];
  __shared__ float Ws[8][128];
  const int which = blockIdx.y;
  const float* __restrict__ W = (which == 0) ? Wq : (which == 1) ? Wk : Wv;
  float* __restrict__ outp = (which == 0) ? g_q : (which == 1) ? g_k : g_v;

  const int m0 = blockIdx.x * 128;
  const int tid = threadIdx.x;
  const int tm = tid >> 4;
  const int tn = tid & 15;
  const int xm = tid >> 1;
  const int xk = (tid & 1) << 2;
  const int wk = tid >> 5;
  const int wn = (tid & 31) << 2;

  ull acc2[8][4];
#pragma unroll
  for (int i = 0; i < 8; i++)
#pragma unroll
    for (int j = 0; j < 4; j++) acc2[i][j] = 0ull;

  for (int k0 = 0; k0 < EE; k0 += 8) {
    float4 xv = *(const float4*)&X[(size_t)(m0 + xm) * EE + k0 + xk];
    float4 wv = *(const float4*)&W[(size_t)(k0 + wk) * DD + wn];
    __syncthreads();
    Xs[xk + 0][xm] = xv.x;
    Xs[xk + 1][xm] = xv.y;
    Xs[xk + 2][xm] = xv.z;
    Xs[xk + 3][xm] = xv.w;
    *(float4*)&Ws[wk][wn] = wv;
    __syncthreads();
#pragma unroll
    for (int kk = 0; kk < 8; kk++) {
      float a[8];
      *(float4*)&a[0] = *(const float4*)&Xs[kk][tm * 8];
      *(float4*)&a[4] = *(const float4*)&Xs[kk][tm * 8 + 4];
      ulonglong2 b01 = *(const ulonglong2*)&Ws[kk][tn * 8];
      ulonglong2 b23 = *(const ulonglong2*)&Ws[kk][tn * 8 + 4];
#pragma unroll
      for (int i = 0; i < 8; i++) {
        ull aa = packf2(a[i], a[i]);
        fma2(acc2[i][0], aa, b01.x);
        fma2(acc2[i][1], aa, b01.y);
        fma2(acc2[i][2], aa, b23.x);
        fma2(acc2[i][3], aa, b23.y);
      }
    }
  }

#pragma unroll
  for (int i = 0; i < 8; i++) {
    size_t row = (size_t)(m0 + tm * 8 + i);
    F2U u0, u1, u2, u3;
    u0.u = acc2[i][0]; u1.u = acc2[i][1];
    u2.u = acc2[i][2]; u3.u = acc2[i][3];
    float4 o0 = make_float4(u0.f.x, u0.f.y, u1.f.x, u1.f.y);
    float4 o1 = make_float4(u2.f.x, u2.f.y, u3.f.x, u3.f.y);
    *(float4*)&outp[row * DD + tn * 8] = o0;
    *(float4*)&outp[row * DD + tn * 8 + 4] = o1;
  }
}

// ---------------------------------------------------------------------------
// Causal flash attention v3: 512 threads (16 warps = 4/SMSP) for latency hiding.
// BQ=64, BK=32, D=128.  Warp w owns rows w*4..w*4+3.
// Thread (g=lane>>3, l8=lane&7): S row w*4+g x cols {l8+8j}.
// Register softmax (shfl in 8-lane groups); P in warp-private strip (stride 40).
// PV: thread accumulates warp's 4 rows x dv=lane*4..+3.
// CTA pairing over qblk for causal balance (grid 16 x 8).
// ---------------------------------------------------------------------------
#define BQ 64
#define BK 32
#define SQ 132
#define SKS 132
#define SV 128
#define SP 40      // P stride per row (banks 8g+l8+8j -> conflict-free)
#define NTHR 512

#define OFF_Q 0
#define OFF_K (OFF_Q + BQ * SQ)          // 8448
#define OFF_V (OFF_K + BK * SKS)         // 12672
#define OFF_P (OFF_V + BK * SV)          // 16768 (16 warps * 4 rows * 40)
#define OFF_AR (OFF_P + 16 * 4 * SP)     // 19328
#define OFF_LR (OFF_AR + BQ)
#define SMEM_FLOATS (OFF_LR + BQ)        // 19456 floats = 77824 B

__global__ __launch_bounds__(NTHR) void attn_kernel(float* __restrict__ out) {
  extern __shared__ float sm_[];
  float* Qs = sm_ + OFF_Q;
  float* Ks = sm_ + OFF_K;
  float* Vs = sm_ + OFF_V;
  float* Ps = sm_ + OFF_P;
  float* arowS = sm_ + OFF_AR;
  float* lrowS = sm_ + OFF_LR;

  const int b = blockIdx.y;
  const int tid = threadIdx.x;
  const int w = tid >> 5;
  const int lane = tid & 31;
  const int g = lane >> 3;
  const int l8 = lane & 7;
  const float* __restrict__ qp = g_q + (size_t)b * TT * DD;
  const float* __restrict__ kp = g_k + (size_t)b * TT * DD;
  const float* __restrict__ vp = g_v + (size_t)b * TT * DD;
  const float scale = 0.08838834764831845f;  // 1/sqrt(128)

  const int r0 = w * 4 + g;          // this thread's softmax row (local)
  float* Pw = Ps + w * 4 * SP;       // warp-private P strip [4][SP]

  for (int pass = 0; pass < 2; pass++) {
    const int qblk = pass ? (TT / BQ - 1 - (int)blockIdx.x) : (int)blockIdx.x;
    __syncthreads();  // previous pass done with Qs

    // Load Q tile (pre-scaled): 64x128 = 2048 float4 / 512 threads
#pragma unroll
    for (int it = 0; it < 4; it++) {
      int idx = tid + it * NTHR;
      int r = idx >> 5;
      int d4 = (idx & 31) << 2;
      float4 v = *(const float4*)&qp[(size_t)(qblk * BQ + r) * DD + d4];
      v.x *= scale; v.y *= scale; v.z *= scale; v.w *= scale;
      *(float4*)&Qs[r * SQ + d4] = v;
    }

    float mrow = -1e30f, lrow = 0.f;
    ull o2[4][2];
#pragma unroll
    for (int r = 0; r < 4; r++) { o2[r][0] = 0ull; o2[r][1] = 0ull; }

    const int nkt = 2 * (qblk + 1);
    for (int kt = 0; kt < nkt; kt++) {
      // Load K,V tiles: 32x128 each = 1024 float4 / 512 threads
#pragma unroll
      for (int it = 0; it < 2; it++) {
        int idx = tid + it * NTHR;
        int r = idx >> 5;
        int d4 = (idx & 31) << 2;
        float4 kv = *(const float4*)&kp[(size_t)(kt * BK + r) * DD + d4];
        *(float4*)&Ks[r * SKS + d4] = kv;
        float4 vv = *(const float4*)&vp[(size_t)(kt * BK + r) * DD + d4];
        *(float4*)&Vs[r * SV + d4] = vv;
      }
      __syncthreads();

      // ---- S = Q K^T : 1 row x 4 cols per thread ----
      float s0 = 0.f, s1 = 0.f, s2 = 0.f, s3 = 0.f;
#pragma unroll 8
      for (int d = 0; d < DD; d += 4) {
        float4 q0 = *(const float4*)&Qs[r0 * SQ + d];
        float4 k0 = *(const float4*)&Ks[l8 * SKS + d];
        float4 k1 = *(const float4*)&Ks[(l8 + 8) * SKS + d];
        float4 k2 = *(const float4*)&Ks[(l8 + 16) * SKS + d];
        float4 k3 = *(const float4*)&Ks[(l8 + 24) * SKS + d];
        s0 += q0.x * k0.x + q0.y * k0.y + q0.z * k0.z + q0.w * k0.w;
        s1 += q0.x * k1.x + q0.y * k1.y + q0.z * k1.z + q0.w * k1.w;
        s2 += q0.x * k2.x + q0.y * k2.y + q0.z * k2.z + q0.w * k2.w;
        s3 += q0.x * k3.x + q0.y * k3.y + q0.z * k3.z + q0.w * k3.w;
      }

      // Causal mask (diagonal tiles only)
      if (kt >= 2 * qblk) {
        const int qg = qblk * BQ + r0;
        if (kt * BK + l8 > qg) s0 = -1e30f;
        if (kt * BK + l8 + 8 > qg) s1 = -1e30f;
        if (kt * BK + l8 + 16 > qg) s2 = -1e30f;
        if (kt * BK + l8 + 24 > qg) s3 = -1e30f;
      }

      // ---- online softmax (register-resident, 8-lane reductions) ----
      float vmax = fmaxf(fmaxf(s0, s1), fmaxf(s2, s3));
#pragma unroll
      for (int off = 1; off < 8; off <<= 1)
        vmax = fmaxf(vmax, __shfl_xor_sync(0xffffffffu, vmax, off));
      float mn = fmaxf(mrow, vmax);
      float al = __expf(mrow - mn);
      float p0 = __expf(s0 - mn);
      float p1 = __expf(s1 - mn);
      float p2 = __expf(s2 - mn);
      float p3 = __expf(s3 - mn);
      float ps = p0 + p1 + p2 + p3;
#pragma unroll
      for (int off = 1; off < 8; off <<= 1)
        ps += __shfl_xor_sync(0xffffffffu, ps, off);
      lrow = lrow * al + ps;
      mrow = mn;
      // P write: banks (8g + l8 + 8j) all distinct per store
      Pw[g * SP + l8] = p0;
      Pw[g * SP + l8 + 8] = p1;
      Pw[g * SP + l8 + 16] = p2;
      Pw[g * SP + l8 + 24] = p3;
      if (l8 == 0) arowS[r0] = al;
      __syncwarp();

      // ---- rescale O by the warp's 4 row alphas ----
#pragma unroll
      for (int r = 0; r < 4; r++) {
        float a = arowS[w * 4 + r];
        ull aa = packf2(a, a);
        o2[r][0] = mul2(o2[r][0], aa);
        o2[r][1] = mul2(o2[r][1], aa);
      }

      // ---- O += P @ V ----
#pragma unroll 2
      for (int k4 = 0; k4 < 8; k4++) {
        ulonglong2 vv[4];
#pragma unroll
        for (int kk = 0; kk < 4; kk++)
          vv[kk] = *(const ulonglong2*)&Vs[(k4 * 4 + kk) * SV + lane * 4];
#pragma unroll
        for (int r = 0; r < 4; r++) {
          float4 p4 = *(const float4*)&Pw[r * SP + k4 * 4];
          ull pp;
          pp = packf2(p4.x, p4.x);
          fma2(o2[r][0], pp, vv[0].x); fma2(o2[r][1], pp, vv[0].y);
          pp = packf2(p4.y, p4.y);
          fma2(o2[r][0], pp, vv[1].x); fma2(o2[r][1], pp, vv[1].y);
          pp = packf2(p4.z, p4.z);
          fma2(o2[r][0], pp, vv[2].x); fma2(o2[r][1], pp, vv[2].y);
          pp = packf2(p4.w, p4.w);
          fma2(o2[r][0], pp, vv[3].x); fma2(o2[r][1], pp, vv[3].y);
        }
      }
      __syncthreads();  // K/V consumed; safe to overwrite next tile
    }

    // ---- epilogue ----
    if (l8 == 0) lrowS[r0] = lrow;
    __syncwarp();
#pragma unroll
    for (int r = 0; r < 4; r++) {
      float inv = 1.f / lrowS[w * 4 + r];
      F2U u0, u1;
      u0.u = o2[r][0]; u1.u = o2[r][1];
      size_t base = ((size_t)b * TT + (size_t)qblk * BQ + w * 4 + r) * DD;
      float4 ov = make_float4(u0.f.x * inv, u0.f.y * inv,
                              u1.f.x * inv, u1.f.y * inv);
      *(float4*)&out[base + lane * 4] = ov;
    }
  }
}

// ---------------------------------------------------------------------------
extern "C" void kernel_launch(void* const* d_in, const int* in_sizes, int n_in,
                              void* d_out, int out_size) {
  const float* X = (const float*)d_in[0];
  const float* Wq = (const float*)d_in[1];
  const float* Wk = (const float*)d_in[2];
  const float* Wv = (const float*)d_in[3];
  float* out = (float*)d_out;

  qkv_gemm_kernel<<<dim3(128, 3), 256>>>(X, Wq, Wk, Wv);

  const int smem_bytes = SMEM_FLOATS * (int)sizeof(float);
  cudaFuncSetAttribute((const void*)attn_kernel,
                       cudaFuncAttributeMaxDynamicSharedMemorySize, smem_bytes);
  attn_kernel<<<dim3(16, BATCHN), NTHR, smem_bytes>>>(out);
}